// round 2
// baseline (speedup 1.0000x reference)
#include <cuda_runtime.h>
#include <stdint.h>

#define BATCH 16
#define CIN   64
#define CF    64
#define FH    45
#define FW    80
#define NANCH 2784
#define KOUT  75    // 2 cls + 73 reg
#define OUTW  77

// Scratch (static __device__ — allocation-free per harness rules)
__device__ float g_W2[CIN * FH * KOUT];        // [cin][y][k]
__device__ float g_cb[FH * KOUT];              // conv-bias folded per (y,k)
__device__ float g_A[BATCH * FH * FW * KOUT];  // [b][y][x][k]  (17.3 MB, L2-resident)

// ---------------------------------------------------------------------------
// Kernel 1: W2[cin,y,k] = sum_cf conv_w[cf,cin] * Wcat[cf*FH+y, k]
//           cb[y,k]     = sum_cf conv_b[cf]     * Wcat[cf*FH+y, k]
// ---------------------------------------------------------------------------
__global__ void prep_kernel(const float* __restrict__ conv_w,
                            const float* __restrict__ conv_b,
                            const float* __restrict__ cls_w,
                            const float* __restrict__ reg_w) {
    const int W2N = CIN * FH * KOUT;
    int idx = blockIdx.x * blockDim.x + threadIdx.x;
    if (idx < W2N) {
        int k   = idx % KOUT;
        int y   = (idx / KOUT) % FH;
        int cin = idx / (KOUT * FH);
        float acc = 0.f;
        #pragma unroll 4
        for (int cf = 0; cf < CF; ++cf) {
            float ws = (k < 2) ? cls_w[(cf * FH + y) * 2 + k]
                               : reg_w[(cf * FH + y) * 73 + (k - 2)];
            acc += conv_w[cf * CIN + cin] * ws;
        }
        g_W2[idx] = acc;
    } else if (idx < W2N + FH * KOUT) {
        int j = idx - W2N;
        int k = j % KOUT;
        int y = j / KOUT;
        float acc = 0.f;
        #pragma unroll 4
        for (int cf = 0; cf < CF; ++cf) {
            float ws = (k < 2) ? cls_w[(cf * FH + y) * 2 + k]
                               : reg_w[(cf * FH + y) * 73 + (k - 2)];
            acc += conv_b[cf] * ws;
        }
        g_cb[j] = acc;
    }
}

// ---------------------------------------------------------------------------
// Kernel 2: A[b,y,x,k] = cb[y,k] + sum_cin x[b,cin,y,x] * W2[cin,y,k]
// One block per (y, b). Register tiling 4(x) x 5(k) per thread, 300 active.
// ---------------------------------------------------------------------------
__global__ void __launch_bounds__(320) a_kernel(const float* __restrict__ x) {
    __shared__ float xs_s[CIN * FW];    // 20 KB
    __shared__ float w_s[CIN * KOUT];   // 19.2 KB
    __shared__ float cb_s[KOUT];

    int y = blockIdx.x;
    int b = blockIdx.y;
    int t = threadIdx.x;

    for (int i = t; i < CIN * FW; i += 320) {
        int cin = i / FW, xx = i % FW;
        xs_s[i] = x[((b * CIN + cin) * FH + y) * FW + xx];
    }
    for (int i = t; i < CIN * KOUT; i += 320) {
        int cin = i / KOUT, k = i % KOUT;
        w_s[i] = g_W2[(cin * FH + y) * KOUT + k];
    }
    if (t < KOUT) cb_s[t] = g_cb[y * KOUT + t];
    __syncthreads();

    if (t >= 300) return;
    int kt = t % 15, xt = t / 15;
    int k0 = kt * 5, x0 = xt * 4;

    float acc[4][5];
    #pragma unroll
    for (int j = 0; j < 4; ++j)
        #pragma unroll
        for (int i = 0; i < 5; ++i) acc[j][i] = 0.f;

    #pragma unroll 4
    for (int cin = 0; cin < CIN; ++cin) {
        float xv[4], wv[5];
        #pragma unroll
        for (int j = 0; j < 4; ++j) xv[j] = xs_s[cin * FW + x0 + j];
        #pragma unroll
        for (int i = 0; i < 5; ++i) wv[i] = w_s[cin * KOUT + k0 + i];
        #pragma unroll
        for (int j = 0; j < 4; ++j)
            #pragma unroll
            for (int i = 0; i < 5; ++i) acc[j][i] += xv[j] * wv[i];
    }

    float* Ab = g_A + (size_t)((b * FH + y) * FW) * KOUT;
    #pragma unroll
    for (int j = 0; j < 4; ++j)
        #pragma unroll
        for (int i = 0; i < 5; ++i)
            Ab[(x0 + j) * KOUT + (k0 + i)] = acc[j][i] + cb_s[k0 + i];
}

// ---------------------------------------------------------------------------
// Kernel 3: gather-reduce over y with per-(b,y) tile staged in smem.
// Block = (b, chunk of NL=232 anchors). 600 active threads = 75 k x 8 groups,
// each thread accumulates 29 anchors.
// ---------------------------------------------------------------------------
#define NL    232
#define GRPS  8
#define ACCN  29   // NL / GRPS
#define GTHREADS 608

__global__ void __launch_bounds__(GTHREADS) gather_kernel(
    const int*     __restrict__ cut_xs,
    const uint8_t* __restrict__ invalid,
    const float*   __restrict__ anchors,
    const float*   __restrict__ cls_b,
    const float*   __restrict__ reg_b,
    float*         __restrict__ out)
{
    __shared__ __align__(16) float A_s[FW * KOUT];   // 24 KB
    __shared__ uint8_t xs8[NL * FH];                 // 10.4 KB

    int b  = blockIdx.y;
    int n0 = blockIdx.x * NL;
    int t  = threadIdx.x;

    // Coalesced load of column indices + invalid flag, packed to 1 byte.
    for (int i = t; i < NL * FH; i += GTHREADS) {
        int xc = cut_xs[n0 * FH + i];
        uint8_t inv = invalid[n0 * FH + i];
        xs8[i] = inv ? (uint8_t)0x80 : (uint8_t)xc;
    }

    float acc[ACCN];
    #pragma unroll
    for (int j = 0; j < ACCN; ++j) acc[j] = 0.f;

    int k   = t % KOUT;
    int grp = t / KOUT;            // 0..7 when t < 600
    bool active = (t < GRPS * KOUT);

    for (int y = 0; y < FH; ++y) {
        __syncthreads();           // protect A_s reuse + xs8 init on y==0
        const float4* src = (const float4*)(g_A + (size_t)((b * FH + y) * FW) * KOUT);
        float4* dst = (float4*)A_s;
        #pragma unroll
        for (int i = t; i < (FW * KOUT) / 4; i += GTHREADS) dst[i] = src[i];
        __syncthreads();

        if (active) {
            #pragma unroll
            for (int j = 0; j < ACCN; ++j) {
                int nl = grp + j * GRPS;
                unsigned c = xs8[nl * FH + y];
                if (!(c & 0x80u)) acc[j] += A_s[c * KOUT + k];
            }
        }
    }

    if (!active) return;

    float bias = (k < 2) ? cls_b[k] : reg_b[k - 2];
    #pragma unroll
    for (int j = 0; j < ACCN; ++j) {
        int n = n0 + grp + j * GRPS;
        float* o = out + (size_t)(b * NANCH + n) * OUTW;
        if (k < 2) {
            o[k]     = acc[j] + bias;
            o[k + 2] = anchors[(size_t)n * OUTW + (k + 2)];   // p24 passthrough
        } else {
            o[k + 2] = acc[j] + bias + anchors[(size_t)n * OUTW + (k + 2)];
        }
    }
}

// ---------------------------------------------------------------------------
extern "C" void kernel_launch(void* const* d_in, const int* in_sizes, int n_in,
                              void* d_out, int out_size) {
    const float*   x        = (const float*)d_in[0];
    const float*   conv_w   = (const float*)d_in[1];
    const float*   conv_b   = (const float*)d_in[2];
    const float*   cls_w    = (const float*)d_in[3];
    const float*   cls_b    = (const float*)d_in[4];
    const float*   reg_w    = (const float*)d_in[5];
    const float*   reg_b    = (const float*)d_in[6];
    const float*   anchors  = (const float*)d_in[7];
    const int*     cut_xs   = (const int*)d_in[8];
    const uint8_t* invalid  = (const uint8_t*)d_in[9];
    float* out = (float*)d_out;

    int prep_total = CIN * FH * KOUT + FH * KOUT;
    prep_kernel<<<(prep_total + 255) / 256, 256>>>(conv_w, conv_b, cls_w, reg_w);

    dim3 agrid(FH, BATCH);
    a_kernel<<<agrid, 320>>>(x);

    dim3 ggrid(NANCH / NL, BATCH);
    gather_kernel<<<ggrid, GTHREADS>>>(cut_xs, invalid, anchors, cls_b, reg_b, out);
}

// round 3
// speedup vs baseline: 1.3241x; 1.3241x over previous
#include <cuda_runtime.h>
#include <stdint.h>

#define BATCH 16
#define CIN   64
#define CF    64
#define FH    45
#define FW    80
#define NANCH 2784
#define KOUT  75
#define KPAD  80    // padded K (cols 75..79 are zero)
#define OUTW  77

typedef unsigned long long ull;

// ---------------------------------------------------------------------------
// Scratch (static __device__ — allocation-free)
// ---------------------------------------------------------------------------
__device__ float g_W2[FH * CIN * KPAD];          // [y][cin][k]  (1.47 MB)
__device__ float g_cb[FH * KPAD];                // [y][k]
__device__ float g_A[BATCH * FH * FW * KPAD];    // [b][y][x][k] (18.4 MB, L2)

// ---------------------------------------------------------------------------
// f32x2 packed-math helpers (sm_103a)
// ---------------------------------------------------------------------------
__device__ __forceinline__ ull ffma2(ull a, ull b, ull c) {
    ull d;
    asm("fma.rn.f32x2 %0, %1, %2, %3;" : "=l"(d) : "l"(a), "l"(b), "l"(c));
    return d;
}
__device__ __forceinline__ ull add2(ull a, ull b) {
    ull r;
    asm("add.rn.f32x2 %0, %1, %2;" : "=l"(r) : "l"(a), "l"(b));
    return r;
}
__device__ __forceinline__ ull pk2(float x) {
    ull r;
    asm("mov.b64 %0, {%1, %1};" : "=l"(r) : "f"(x));
    return r;
}
__device__ __forceinline__ void cpa16(uint32_t s, const void* g) {
    asm volatile("cp.async.ca.shared.global [%0], [%1], 16;" :: "r"(s), "l"(g));
}
__device__ __forceinline__ void cpa_commit() {
    asm volatile("cp.async.commit_group;");
}
template <int N>
__device__ __forceinline__ void cpa_wait() {
    asm volatile("cp.async.wait_group %0;" :: "n"(N));
}

// ---------------------------------------------------------------------------
// Kernel 1 (prep): one block per y.
//   W2[y][cin][k] = sum_cf conv_w[cf][cin] * Wy[cf][k]
//   cb[y][k]      = sum_cf conv_b[cf]      * Wy[cf][k]
// Wy[cf][k] = cls_w[(cf*45+y)*2 + k] (k<2) | reg_w[(cf*45+y)*73 + k-2] (k<75) | 0
// ---------------------------------------------------------------------------
__global__ void __launch_bounds__(256) prep_kernel(
    const float* __restrict__ conv_w, const float* __restrict__ conv_b,
    const float* __restrict__ cls_w,  const float* __restrict__ reg_w)
{
    __shared__ float cw_s[CF * CIN];   // 16 KB  [cf][cin]
    __shared__ float wy_s[CF * KPAD];  // 20.5 KB [cf][k]

    int y = blockIdx.x;
    int t = threadIdx.x;

    for (int i = t; i < CF * CIN; i += 256) cw_s[i] = conv_w[i];
    for (int i = t; i < CF * KPAD; i += 256) {
        int cf = i / KPAD, k = i % KPAD;
        float v = 0.f;
        if (k < 2)       v = cls_w[(cf * FH + y) * 2 + k];
        else if (k < 75) v = reg_w[(cf * FH + y) * 73 + (k - 2)];
        wy_s[i] = v;
    }
    __syncthreads();

    int cin = t & 63;
    int k0  = (t >> 6) * 20;   // 4 chunks of 20 -> covers 80
    float acc[20];
    #pragma unroll
    for (int j = 0; j < 20; ++j) acc[j] = 0.f;

    #pragma unroll 4
    for (int cf = 0; cf < CF; ++cf) {
        float a = cw_s[cf * CIN + cin];
        #pragma unroll
        for (int j = 0; j < 20; ++j) acc[j] += a * wy_s[cf * KPAD + k0 + j];
    }
    float* w2 = g_W2 + (size_t)y * CIN * KPAD + cin * KPAD + k0;
    #pragma unroll
    for (int j = 0; j < 20; ++j) w2[j] = acc[j];

    if (t < KPAD) {
        float s = 0.f;
        #pragma unroll 4
        for (int cf = 0; cf < CF; ++cf) s += conv_b[cf] * wy_s[cf * KPAD + t];
        g_cb[y * KPAD + t] = s;
    }
}

// ---------------------------------------------------------------------------
// Kernel 2 (A-GEMM, f32x2): block per (y, b). 100 compute threads,
// each owns an 8(x) x 8(k) tile -> acc = 8x4 f32x2 pairs.
// A[b,y,x,k] = cb[y,k] + sum_cin x[b,cin,y,x] * W2[y,cin,k]
// ---------------------------------------------------------------------------
__global__ void __launch_bounds__(128, 5) a_kernel(const float* __restrict__ x) {
    __shared__ float xs_s[CIN * FW];    // 20 KB   [cin][x]
    __shared__ float w_s[CIN * KPAD];   // 20.5 KB [cin][k]
    __shared__ float cb_s[KPAD];

    int y = blockIdx.x;
    int b = blockIdx.y;
    int t = threadIdx.x;

    // x slab: per cin one contiguous 80-float row (float4 loads)
    for (int i4 = t; i4 < CIN * FW / 4; i4 += 128) {
        int cin = i4 / 20, xx4 = i4 % 20;
        const float4* src = (const float4*)(x + ((size_t)(b * CIN + cin) * FH + y) * FW);
        ((float4*)xs_s)[cin * 20 + xx4] = src[xx4];
    }
    // W2 slab for this y: contiguous
    {
        const float4* src = (const float4*)(g_W2 + (size_t)y * CIN * KPAD);
        for (int i4 = t; i4 < CIN * KPAD / 4; i4 += 128) ((float4*)w_s)[i4] = src[i4];
    }
    if (t < KPAD) cb_s[t] = g_cb[y * KPAD + t];
    __syncthreads();

    if (t >= 100) return;
    int xg = t / 10, kg = t % 10;
    int x0 = xg * 8, k0 = kg * 8;

    ull acc[8][4];
    {
        ulonglong2 c01 = *(const ulonglong2*)&cb_s[k0];
        ulonglong2 c23 = *(const ulonglong2*)&cb_s[k0 + 4];
        #pragma unroll
        for (int i = 0; i < 8; ++i) {
            acc[i][0] = c01.x; acc[i][1] = c01.y;
            acc[i][2] = c23.x; acc[i][3] = c23.y;
        }
    }

    #pragma unroll 2
    for (int cin = 0; cin < CIN; ++cin) {
        float4 xa = *(const float4*)&xs_s[cin * FW + x0];
        float4 xb = *(const float4*)&xs_s[cin * FW + x0 + 4];
        ulonglong2 wA = *(const ulonglong2*)&w_s[cin * KPAD + k0];
        ulonglong2 wB = *(const ulonglong2*)&w_s[cin * KPAD + k0 + 4];
        float xv[8] = {xa.x, xa.y, xa.z, xa.w, xb.x, xb.y, xb.z, xb.w};
        #pragma unroll
        for (int i = 0; i < 8; ++i) {
            ull px = pk2(xv[i]);
            acc[i][0] = ffma2(px, wA.x, acc[i][0]);
            acc[i][1] = ffma2(px, wA.y, acc[i][1]);
            acc[i][2] = ffma2(px, wB.x, acc[i][2]);
            acc[i][3] = ffma2(px, wB.y, acc[i][3]);
        }
    }

    float* Ab = g_A + ((size_t)(b * FH + y) * FW) * KPAD;
    #pragma unroll
    for (int i = 0; i < 8; ++i) {
        ulonglong2* dst = (ulonglong2*)(Ab + (x0 + i) * KPAD + k0);
        dst[0] = make_ulonglong2(acc[i][0], acc[i][1]);
        dst[1] = make_ulonglong2(acc[i][2], acc[i][3]);
    }
}

// ---------------------------------------------------------------------------
// Kernel 3 (gather-reduce): block per (b, chunk of NL=348 anchors).
// 456 compute threads = 38 k-pairs x 12 anchor-groups; ACCN = 29 anchors each.
// Double-buffered cp.async staging of the (b,y) A tile; zeroed 81st row makes
// invalid anchors branchless (index 80 -> zeros).
// ---------------------------------------------------------------------------
#define NL       348
#define GRPS     12
#define ACCN     29          // NL / GRPS
#define GTHREADS 480
#define ROWB     (FW * 4)                 // 320 bytes per x-row
#define BUFB     ((FW + 1) * ROWB)        // 81 rows = 25920 B
#define XSROW    384                      // padded [y] row: 12 grps * 32
#define SMEM_GATHER (2 * BUFB + FH * XSROW)   // 51840 + 17280 = 69120

__global__ void __launch_bounds__(GTHREADS) gather_kernel(
    const int*     __restrict__ cut_xs,
    const uint8_t* __restrict__ invalid,
    const float*   __restrict__ anchors,
    const float*   __restrict__ cls_b,
    const float*   __restrict__ reg_b,
    float*         __restrict__ out)
{
    extern __shared__ char smem[];
    char*    bufs = smem;                      // 2 x 25920 B
    uint8_t* xs8  = (uint8_t*)(smem + 2 * BUFB);

    int b  = blockIdx.y;
    int n0 = blockIdx.x * NL;
    int t  = threadIdx.x;

    // Zero the pad row (row 80) of both buffers.
    for (int i = t; i < 2 * FW; i += GTHREADS) {
        int buf = i / FW, xx = i % FW;
        ((float*)(bufs + buf * BUFB + FW * ROWB))[xx] = 0.f;
    }
    // Stage per-anchor column indices (invalid -> 80, the zero row),
    // layout xs8[y][grp*32 + j] for aligned uint4 reads.
    for (int i = t; i < NL * FH; i += GTHREADS) {
        int nl = i / FH, yy = i % FH;
        int xc = cut_xs[(size_t)(n0 + nl) * FH + yy];
        if (invalid[(size_t)(n0 + nl) * FH + yy]) xc = FW;
        int grp = nl / ACCN, j = nl % ACCN;
        xs8[yy * XSROW + grp * 32 + j] = (uint8_t)xc;
    }

    const char* Ab = (const char*)(g_A + (size_t)b * FH * FW * KPAD);

    // Prefetch y=0 into buffer 0.
    {
        uint32_t sdst = (uint32_t)__cvta_generic_to_shared(bufs);
        for (int i = t; i < FW * KPAD / 4; i += GTHREADS)
            cpa16(sdst + i * 16, Ab + i * 16);
        cpa_commit();
    }

    int grp = t / 38, kp = t % 38;
    bool active = (grp < GRPS);
    uint32_t xsoff = grp * 32;

    ull acc[ACCN];
    #pragma unroll
    for (int j = 0; j < ACCN; ++j) acc[j] = 0;

    #pragma unroll 1
    for (int y = 0; y < FH; ++y) {
        int cur = y & 1;
        __syncthreads();   // buf(1-cur) free (prev compute done); xs visible (y==0)
        if (y + 1 < FH) {
            uint32_t sdst = (uint32_t)__cvta_generic_to_shared(bufs + (1 - cur) * BUFB);
            const char* src = Ab + (size_t)(y + 1) * FW * KPAD * 4;
            for (int i = t; i < FW * KPAD / 4; i += GTHREADS)
                cpa16(sdst + i * 16, src + i * 16);
            cpa_commit();
            cpa_wait<1>();
        } else {
            cpa_wait<0>();
        }
        __syncthreads();   // buf(cur) visible

        if (active) {
            const char* A_s = bufs + cur * BUFB + kp * 8;
            const uint4* xw = (const uint4*)(xs8 + y * XSROW + xsoff);
            uint4 u0 = xw[0];
            uint4 u1 = xw[1];
            uint32_t uw[8] = {u0.x, u0.y, u0.z, u0.w, u1.x, u1.y, u1.z, u1.w};
            #pragma unroll
            for (int j = 0; j < ACCN; ++j) {
                uint32_t c = (uw[j >> 2] >> ((j & 3) * 8)) & 0xFFu;
                ull v = *(const ull*)(A_s + c * ROWB);
                acc[j] = add2(acc[j], v);
            }
        }
    }

    if (!active) return;

    // Epilogue: biases + anchor offsets, scatter to out.
    int k = 2 * kp;                  // k, k+1 of the 76-wide padded result
    float b0 = (kp == 0) ? cls_b[0] : reg_b[k - 2];
    float b1 = (kp == 0) ? cls_b[1] : ((kp < 37) ? reg_b[k - 1] : 0.f);

    #pragma unroll 4
    for (int j = 0; j < ACCN; ++j) {
        int n = n0 + grp * ACCN + j;
        float* o = out + (size_t)(b * NANCH + n) * OUTW;
        const float* an = anchors + (size_t)n * OUTW;
        float lo = __uint_as_float((uint32_t)(acc[j] & 0xFFFFFFFFull));
        float hi = __uint_as_float((uint32_t)(acc[j] >> 32));
        if (kp == 0) {
            o[0] = lo + b0;
            o[1] = hi + b1;
            o[2] = an[2];
            o[3] = an[3];
        } else if (kp < 37) {
            o[k + 2] = lo + b0 + an[k + 2];
            o[k + 3] = hi + b1 + an[k + 3];
        } else {           // kp == 37: k=74 valid, k=75 is padding
            o[76] = lo + b0 + an[76];
        }
    }
}

// ---------------------------------------------------------------------------
extern "C" void kernel_launch(void* const* d_in, const int* in_sizes, int n_in,
                              void* d_out, int out_size) {
    const float*   x        = (const float*)d_in[0];
    const float*   conv_w   = (const float*)d_in[1];
    const float*   conv_b   = (const float*)d_in[2];
    const float*   cls_w    = (const float*)d_in[3];
    const float*   cls_b    = (const float*)d_in[4];
    const float*   reg_w    = (const float*)d_in[5];
    const float*   reg_b    = (const float*)d_in[6];
    const float*   anchors  = (const float*)d_in[7];
    const int*     cut_xs   = (const int*)d_in[8];
    const uint8_t* invalid  = (const uint8_t*)d_in[9];
    float* out = (float*)d_out;

    static int smem_set = 0;
    if (!smem_set) {
        cudaFuncSetAttribute(gather_kernel,
                             cudaFuncAttributeMaxDynamicSharedMemorySize,
                             SMEM_GATHER);
        smem_set = 1;
    }

    prep_kernel<<<FH, 256>>>(conv_w, conv_b, cls_w, reg_w);

    dim3 agrid(FH, BATCH);
    a_kernel<<<agrid, 128>>>(x);

    dim3 ggrid(NANCH / NL, BATCH);
    gather_kernel<<<ggrid, GTHREADS, SMEM_GATHER>>>(cut_xs, invalid, anchors,
                                                    cls_b, reg_b, out);
}

// round 7
// speedup vs baseline: 1.3998x; 1.0572x over previous
#include <cuda_runtime.h>
#include <stdint.h>

#define BATCH 16
#define CIN   64
#define CF    64
#define FH    45
#define FW    80
#define NANCH 2784
#define KOUT  75
#define KPAD  80    // padded K (cols 75..79 are zero)
#define OUTW  77

typedef unsigned long long ull;

// ---------------------------------------------------------------------------
// Scratch (static __device__ — allocation-free)
// ---------------------------------------------------------------------------
__device__ float g_W2[FH * CIN * KPAD];          // [y][cin][k]  (1.47 MB)
__device__ float g_cb[FH * KPAD];                // [y][k]
__device__ float g_A[BATCH * FH * FW * KPAD];    // [b][y][x][k] (18.4 MB, L2)

// ---------------------------------------------------------------------------
// f32x2 packed-math helpers (sm_103a)
// ---------------------------------------------------------------------------
__device__ __forceinline__ ull ffma2(ull a, ull b, ull c) {
    ull d;
    asm("fma.rn.f32x2 %0, %1, %2, %3;" : "=l"(d) : "l"(a), "l"(b), "l"(c));
    return d;
}
__device__ __forceinline__ ull add2(ull a, ull b) {
    ull r;
    asm("add.rn.f32x2 %0, %1, %2;" : "=l"(r) : "l"(a), "l"(b));
    return r;
}
__device__ __forceinline__ ull pk2(float x) {
    ull r;
    asm("mov.b64 %0, {%1, %1};" : "=l"(r) : "f"(x));
    return r;
}
__device__ __forceinline__ void cpa16(uint32_t s, const void* g) {
    asm volatile("cp.async.ca.shared.global [%0], [%1], 16;" :: "r"(s), "l"(g));
}
__device__ __forceinline__ void cpa_commit() {
    asm volatile("cp.async.commit_group;");
}
template <int N>
__device__ __forceinline__ void cpa_wait() {
    asm volatile("cp.async.wait_group %0;" :: "n"(N));
}

// ---------------------------------------------------------------------------
// Kernel 1 (prep): grid (kq=4, y=45). Block computes W2[y][0:64][kq*20:+20].
//   W2[y][cin][k] = sum_cf conv_w[cf][cin] * Wy[cf][k]
//   cb[y][k]      = sum_cf conv_b[cf]      * Wy[cf][k]
// ---------------------------------------------------------------------------
__global__ void __launch_bounds__(256) prep_kernel(
    const float* __restrict__ conv_w, const float* __restrict__ conv_b,
    const float* __restrict__ cls_w,  const float* __restrict__ reg_w)
{
    __shared__ float cw_s[CF * CIN];   // 16 KB [cf][cin]
    __shared__ float wy_s[CF * 20];    // 5 KB  [cf][j]

    int kq = blockIdx.x;
    int y  = blockIdx.y;
    int k0 = kq * 20;
    int t  = threadIdx.x;

    for (int i = t; i < CF * CIN; i += 256) cw_s[i] = conv_w[i];
    for (int i = t; i < CF * 20; i += 256) {
        int cf = i / 20, k = k0 + i % 20;
        float v = 0.f;
        if (k < 2)       v = cls_w[(cf * FH + y) * 2 + k];
        else if (k < 75) v = reg_w[(cf * FH + y) * 73 + (k - 2)];
        wy_s[i] = v;
    }
    __syncthreads();

    int cin = t & 63;
    int j0  = (t >> 6) * 5;   // 4 sub-groups of 5 k
    float acc[5] = {0.f, 0.f, 0.f, 0.f, 0.f};

    #pragma unroll 4
    for (int cf = 0; cf < CF; ++cf) {
        float a = cw_s[cf * CIN + cin];
        #pragma unroll
        for (int j = 0; j < 5; ++j) acc[j] += a * wy_s[cf * 20 + j0 + j];
    }
    float* w2 = g_W2 + ((size_t)y * CIN + cin) * KPAD + k0 + j0;
    #pragma unroll
    for (int j = 0; j < 5; ++j) w2[j] = acc[j];

    if (t < 20) {
        float s = 0.f;
        #pragma unroll 4
        for (int cf = 0; cf < CF; ++cf) s += conv_b[cf] * wy_s[cf * 20 + t];
        g_cb[y * KPAD + k0 + t] = s;
    }
}

// ---------------------------------------------------------------------------
// Kernel 2 (A-GEMM, f32x2): block per (y, b). 160 threads, each owns a
// 5(x) x 8(k) tile -> acc = 5x4 f32x2 pairs (40 regs, no spill).
// A[b,y,x,k] = cb[y,k] + sum_cin x[b,cin,y,x] * W2[y,cin,k]
// ---------------------------------------------------------------------------
__global__ void __launch_bounds__(160) a_kernel(const float* __restrict__ x) {
    __shared__ float xs_s[CIN * FW];    // 20 KB   [cin][x]
    __shared__ float w_s[CIN * KPAD];   // 20.5 KB [cin][k]
    __shared__ float cb_s[KPAD];

    int y = blockIdx.x;
    int b = blockIdx.y;
    int t = threadIdx.x;

    for (int i4 = t; i4 < CIN * FW / 4; i4 += 160) {
        int cin = i4 / 20, xx4 = i4 % 20;
        const float4* src = (const float4*)(x + ((size_t)(b * CIN + cin) * FH + y) * FW);
        ((float4*)xs_s)[cin * 20 + xx4] = src[xx4];
    }
    {
        const float4* src = (const float4*)(g_W2 + (size_t)y * CIN * KPAD);
        for (int i4 = t; i4 < CIN * KPAD / 4; i4 += 160) ((float4*)w_s)[i4] = src[i4];
    }
    if (t < KPAD) cb_s[t] = g_cb[y * KPAD + t];
    __syncthreads();

    int xg = t / 10, kg = t % 10;
    int x0 = xg * 5, k0 = kg * 8;

    ull acc[5][4];
    {
        ulonglong2 c01 = *(const ulonglong2*)&cb_s[k0];
        ulonglong2 c23 = *(const ulonglong2*)&cb_s[k0 + 4];
        #pragma unroll
        for (int i = 0; i < 5; ++i) {
            acc[i][0] = c01.x; acc[i][1] = c01.y;
            acc[i][2] = c23.x; acc[i][3] = c23.y;
        }
    }

    #pragma unroll 4
    for (int cin = 0; cin < CIN; ++cin) {
        ulonglong2 wA = *(const ulonglong2*)&w_s[cin * KPAD + k0];
        ulonglong2 wB = *(const ulonglong2*)&w_s[cin * KPAD + k0 + 4];
        float xv[5];
        #pragma unroll
        for (int i = 0; i < 5; ++i) xv[i] = xs_s[cin * FW + x0 + i];
        #pragma unroll
        for (int i = 0; i < 5; ++i) {
            ull px = pk2(xv[i]);
            acc[i][0] = ffma2(px, wA.x, acc[i][0]);
            acc[i][1] = ffma2(px, wA.y, acc[i][1]);
            acc[i][2] = ffma2(px, wB.x, acc[i][2]);
            acc[i][3] = ffma2(px, wB.y, acc[i][3]);
        }
    }

    float* Ab = g_A + ((size_t)(b * FH + y) * FW) * KPAD;
    #pragma unroll
    for (int i = 0; i < 5; ++i) {
        ulonglong2* dst = (ulonglong2*)(Ab + (x0 + i) * KPAD + k0);
        dst[0] = make_ulonglong2(acc[i][0], acc[i][1]);
        dst[1] = make_ulonglong2(acc[i][2], acc[i][3]);
    }
}

// ---------------------------------------------------------------------------
// Kernel 3 (gather-reduce): block per (b, chunk of NL=348 anchors).
// 456 compute threads = 38 k-pairs x 12 anchor-groups; ACCN = 29 anchors each.
// Double-buffered cp.async staging of the (b,y) A tile; zeroed 81st row makes
// invalid anchors branchless (index 80 -> zeros).
// ---------------------------------------------------------------------------
#define NL       348
#define GRPS     12
#define ACCN     29          // NL / GRPS
#define GTHREADS 480
#define ROWB     (FW * 4)                 // 320 bytes per x-row
#define BUFB     ((FW + 1) * ROWB)        // 81 rows = 25920 B
#define XSROW    384                      // padded [y] row: 12 grps * 32
#define SMEM_GATHER (2 * BUFB + FH * XSROW)   // 51840 + 17280 = 69120

__global__ void __launch_bounds__(GTHREADS) gather_kernel(
    const int*     __restrict__ cut_xs,
    const uint8_t* __restrict__ invalid,
    const float*   __restrict__ anchors,
    const float*   __restrict__ cls_b,
    const float*   __restrict__ reg_b,
    float*         __restrict__ out)
{
    extern __shared__ char smem[];
    char*    bufs = smem;                      // 2 x 25920 B
    uint8_t* xs8  = (uint8_t*)(smem + 2 * BUFB);

    int b  = blockIdx.y;
    int n0 = blockIdx.x * NL;
    int t  = threadIdx.x;

    // Zero the pad row (row 80) of both buffers.
    for (int i = t; i < 2 * FW; i += GTHREADS) {
        int buf = i / FW, xx = i % FW;
        ((float*)(bufs + buf * BUFB + FW * ROWB))[xx] = 0.f;
    }
    // Stage per-anchor column indices (invalid -> 80, the zero row),
    // layout xs8[y][grp*32 + j] for aligned uint4 reads.
    for (int i = t; i < NL * FH; i += GTHREADS) {
        int nl = i / FH, yy = i % FH;
        int xc = cut_xs[(size_t)(n0 + nl) * FH + yy];
        if (invalid[(size_t)(n0 + nl) * FH + yy]) xc = FW;
        int grp = nl / ACCN, j = nl % ACCN;
        xs8[yy * XSROW + grp * 32 + j] = (uint8_t)xc;
    }

    const char* Ab = (const char*)(g_A + (size_t)b * FH * FW * KPAD);

    // Prefetch y=0 into buffer 0.
    {
        uint32_t sdst = (uint32_t)__cvta_generic_to_shared(bufs);
        for (int i = t; i < FW * KPAD / 4; i += GTHREADS)
            cpa16(sdst + i * 16, Ab + i * 16);
        cpa_commit();
    }

    int grp = t / 38, kp = t % 38;
    bool active = (grp < GRPS);
    uint32_t xsoff = grp * 32;

    ull acc[ACCN];
    #pragma unroll
    for (int j = 0; j < ACCN; ++j) acc[j] = 0;

    #pragma unroll 1
    for (int y = 0; y < FH; ++y) {
        int cur = y & 1;
        __syncthreads();   // buf(1-cur) free (prev compute done); xs visible (y==0)
        if (y + 1 < FH) {
            uint32_t sdst = (uint32_t)__cvta_generic_to_shared(bufs + (1 - cur) * BUFB);
            const char* src = Ab + (size_t)(y + 1) * FW * KPAD * 4;
            for (int i = t; i < FW * KPAD / 4; i += GTHREADS)
                cpa16(sdst + i * 16, src + i * 16);
            cpa_commit();
            cpa_wait<1>();
        } else {
            cpa_wait<0>();
        }
        __syncthreads();   // buf(cur) visible

        if (active) {
            const char* A_s = bufs + cur * BUFB + kp * 8;
            const uint4* xw = (const uint4*)(xs8 + y * XSROW + xsoff);
            uint4 u0 = xw[0];
            uint4 u1 = xw[1];
            uint32_t uw[8] = {u0.x, u0.y, u0.z, u0.w, u1.x, u1.y, u1.z, u1.w};
            #pragma unroll
            for (int j = 0; j < ACCN; ++j) {
                uint32_t c = (uw[j >> 2] >> ((j & 3) * 8)) & 0xFFu;
                ull v = *(const ull*)(A_s + c * ROWB);
                acc[j] = add2(acc[j], v);
            }
        }
    }

    if (!active) return;

    // Epilogue: biases + anchor offsets, scatter to out.
    int k = 2 * kp;                  // k, k+1 of the 76-wide padded result
    float b0 = (kp == 0) ? cls_b[0] : reg_b[k - 2];
    float b1 = (kp == 0) ? cls_b[1] : ((kp < 37) ? reg_b[k - 1] : 0.f);

    #pragma unroll 4
    for (int j = 0; j < ACCN; ++j) {
        int n = n0 + grp * ACCN + j;
        float* o = out + (size_t)(b * NANCH + n) * OUTW;
        const float* an = anchors + (size_t)n * OUTW;
        float lo = __uint_as_float((uint32_t)(acc[j] & 0xFFFFFFFFull));
        float hi = __uint_as_float((uint32_t)(acc[j] >> 32));
        if (kp == 0) {
            o[0] = lo + b0;
            o[1] = hi + b1;
            o[2] = an[2];
            o[3] = an[3];
        } else if (kp < 37) {
            o[k + 2] = lo + b0 + an[k + 2];
            o[k + 3] = hi + b1 + an[k + 3];
        } else {           // kp == 37: k=74 valid, k=75 is padding
            o[76] = lo + b0 + an[76];
        }
    }
}

// ---------------------------------------------------------------------------
extern "C" void kernel_launch(void* const* d_in, const int* in_sizes, int n_in,
                              void* d_out, int out_size) {
    const float*   x        = (const float*)d_in[0];
    const float*   conv_w   = (const float*)d_in[1];
    const float*   conv_b   = (const float*)d_in[2];
    const float*   cls_w    = (const float*)d_in[3];
    const float*   cls_b    = (const float*)d_in[4];
    const float*   reg_w    = (const float*)d_in[5];
    const float*   reg_b    = (const float*)d_in[6];
    const float*   anchors  = (const float*)d_in[7];
    const int*     cut_xs   = (const int*)d_in[8];
    const uint8_t* invalid  = (const uint8_t*)d_in[9];
    float* out = (float*)d_out;

    // Idempotent, capture-legal, no static guard (harness forbids them).
    cudaFuncSetAttribute(gather_kernel,
                         cudaFuncAttributeMaxDynamicSharedMemorySize,
                         SMEM_GATHER);

    dim3 pgrid(4, FH);
    prep_kernel<<<pgrid, 256>>>(conv_w, conv_b, cls_w, reg_w);

    dim3 agrid(FH, BATCH);
    a_kernel<<<agrid, 160>>>(x);

    dim3 ggrid(NANCH / NL, BATCH);
    gather_kernel<<<ggrid, GTHREADS, SMEM_GATHER>>>(cut_xs, invalid, anchors,
                                                    cls_b, reg_b, out);
}